// round 2
// baseline (speedup 1.0000x reference)
#include <cuda_runtime.h>
#include <cstdint>

// Problem dims
#define SEQ_L   2048
#define DMODEL  768
#define NHEAD   12
#define DHEAD   64
#define FFDIM   3072
#define VOCAB   50257
#define NLAYER  4

// ---------------------------------------------------------------------------
// Device-global scratch (no allocations allowed)
// ---------------------------------------------------------------------------
__device__ float g_x  [SEQ_L * DMODEL];
__device__ float g_h  [SEQ_L * DMODEL];
__device__ float g_q  [SEQ_L * DMODEL];
__device__ float g_k  [SEQ_L * DMODEL];
__device__ float g_v  [SEQ_L * DMODEL];
__device__ float g_att[SEQ_L * DMODEL];
__device__ float g_ffn[SEQ_L * FFDIM];

// ---------------------------------------------------------------------------
// Helpers
// ---------------------------------------------------------------------------
__device__ __forceinline__ float warp_reduce_sum(float v) {
#pragma unroll
    for (int o = 16; o > 0; o >>= 1) v += __shfl_xor_sync(0xffffffffu, v, o);
    return v;
}
__device__ __forceinline__ float warp_reduce_max(float v) {
#pragma unroll
    for (int o = 16; o > 0; o >>= 1) v = fmaxf(v, __shfl_xor_sync(0xffffffffu, v, o));
    return v;
}
__device__ __forceinline__ float gelu_f(float x) {
    // jax.nn.gelu default (approximate=True, tanh form)
    float x3 = x * x * x;
    return 0.5f * x * (1.0f + tanhf(0.7978845608028654f * (x + 0.044715f * x3)));
}

// ---------------------------------------------------------------------------
// Embedding: x[l,:] = embed[tokens[l],:] + pos[l,:]
// ---------------------------------------------------------------------------
__global__ void embed_kernel(const int* __restrict__ tokens,
                             const float* __restrict__ embed,
                             const float* __restrict__ pos,
                             float* __restrict__ x) {
    int l = blockIdx.x;
    int t = tokens[l];
    const float* er = embed + (size_t)t * DMODEL;
    const float* pr = pos + (size_t)l * DMODEL;
    float* xr = x + (size_t)l * DMODEL;
    for (int d = threadIdx.x; d < DMODEL; d += blockDim.x)
        xr[d] = er[d] + pr[d];
}

// ---------------------------------------------------------------------------
// LayerNorm (one block per row, 256 threads)
// ---------------------------------------------------------------------------
__global__ void ln_kernel(const float* __restrict__ x,
                          const float* __restrict__ gamma,
                          float* __restrict__ out) {
    int l = blockIdx.x;
    const float* row = x + (size_t)l * DMODEL;
    __shared__ float sb_s[8];
    __shared__ float sb_ss[8];
    __shared__ float s_mean, s_rstd;

    float s = 0.f, ss = 0.f;
    for (int d = threadIdx.x; d < DMODEL; d += blockDim.x) {
        float v = row[d];
        s += v; ss += v * v;
    }
    s = warp_reduce_sum(s);
    ss = warp_reduce_sum(ss);
    int warp = threadIdx.x >> 5;
    if ((threadIdx.x & 31) == 0) { sb_s[warp] = s; sb_ss[warp] = ss; }
    __syncthreads();
    if (threadIdx.x == 0) {
        float ts = 0.f, tss = 0.f;
        for (int i = 0; i < 8; i++) { ts += sb_s[i]; tss += sb_ss[i]; }
        float mean = ts * (1.0f / DMODEL);
        float var = tss * (1.0f / DMODEL) - mean * mean;
        s_mean = mean;
        s_rstd = rsqrtf(var + 1e-6f);
    }
    __syncthreads();
    float mean = s_mean, rstd = s_rstd;
    float* o = out + (size_t)l * DMODEL;
    for (int d = threadIdx.x; d < DMODEL; d += blockDim.x)
        o[d] = (row[d] - mean) * rstd * gamma[d];
}

// ---------------------------------------------------------------------------
// Causal attention: one block per (query, head). Two-pass softmax with
// scores staged in shared memory (8 KB).
// ---------------------------------------------------------------------------
__global__ void attn_kernel(const float* __restrict__ q,
                            const float* __restrict__ k,
                            const float* __restrict__ v,
                            float* __restrict__ o) {
    int qi = blockIdx.x;
    int h = blockIdx.y;
    int tid = threadIdx.x;

    __shared__ float sq[DHEAD];
    __shared__ float sc[SEQ_L];
    __shared__ float rbuf[256];
    __shared__ float sred[8];
    __shared__ float s_stat;

    if (tid < DHEAD) sq[tid] = q[(size_t)qi * DMODEL + h * DHEAD + tid];
    __syncthreads();

    int nm = qi + 1;
    int warp = tid >> 5, lane = tid & 31;

    // Phase 1: scores (one warp per key, round-robin)
    for (int m = warp; m < nm; m += 8) {
        const float* kp = k + (size_t)m * DMODEL + h * DHEAD;
        float p = sq[lane] * kp[lane] + sq[lane + 32] * kp[lane + 32];
        p = warp_reduce_sum(p);
        if (lane == 0) sc[m] = p;
    }
    __syncthreads();

    // Phase 2a: max
    float mv = -3.4e38f;
    for (int m = tid; m < nm; m += 256) mv = fmaxf(mv, sc[m]);
    mv = warp_reduce_max(mv);
    if (lane == 0) sred[warp] = mv;
    __syncthreads();
    if (tid == 0) {
        float t = -3.4e38f;
        for (int i = 0; i < 8; i++) t = fmaxf(t, sred[i]);
        s_stat = t;
    }
    __syncthreads();
    mv = s_stat;

    // Phase 2b: exp + sum
    float ssum = 0.f;
    for (int m = tid; m < nm; m += 256) {
        float e = expf(sc[m] - mv);
        sc[m] = e;
        ssum += e;
    }
    ssum = warp_reduce_sum(ssum);
    if (lane == 0) sred[warp] = ssum;
    __syncthreads();
    if (tid == 0) {
        float t = 0.f;
        for (int i = 0; i < 8; i++) t += sred[i];
        s_stat = t;
    }
    __syncthreads();
    float inv = 1.0f / s_stat;

    // Phase 3: o[d] = sum_m p[m] * v[m,h,d]
    int d = tid & 63, part = tid >> 6;
    float acc = 0.f;
    for (int m = part; m < nm; m += 4)
        acc += sc[m] * v[(size_t)m * DMODEL + h * DHEAD + d];
    rbuf[tid] = acc;
    __syncthreads();
    if (part == 0)
        o[(size_t)qi * DMODEL + h * DHEAD + d] =
            (rbuf[d] + rbuf[64 + d] + rbuf[128 + d] + rbuf[192 + d]) * inv;
}

// ---------------------------------------------------------------------------
// Tiled fp32 GEMM: C[M,N] = alpha * A[M,K] @ B  (+ residual) (gelu)
//   BT = false: B is [K,N] row-major
//   BT = true : B is [N,K] row-major (C = alpha * A @ B^T)
// 64x64 block tile, BK=16, 256 threads, 4x4 per-thread microtile.
// M must be a multiple of 64; K a multiple of 16; N arbitrary (guarded).
// ---------------------------------------------------------------------------
template <bool BT, bool RES, bool GELU_>
__global__ void gemm_kernel(const float* __restrict__ A,
                            const float* __restrict__ B,
                            float* __restrict__ C,
                            const float* __restrict__ Rsrc,
                            int M, int N, int K, float alpha) {
    __shared__ float As[16][65];
    __shared__ float Bs[16][68];
    int tid = threadIdx.x;
    int tx = tid & 15, ty = tid >> 4;
    int bm = blockIdx.y * 64, bn = blockIdx.x * 64;

    float acc[4][4];
#pragma unroll
    for (int i = 0; i < 4; i++)
#pragma unroll
        for (int j = 0; j < 4; j++) acc[i][j] = 0.f;

    for (int k0 = 0; k0 < K; k0 += 16) {
        // A tile: 64 rows x 16 cols (always in-bounds)
        {
            int r = tid >> 2;
            int c = (tid & 3) << 2;
            float4 va = *(const float4*)(A + (size_t)(bm + r) * K + k0 + c);
            As[c][r] = va.x; As[c + 1][r] = va.y;
            As[c + 2][r] = va.z; As[c + 3][r] = va.w;
        }
        if (!BT) {
            // B tile: 16 rows (k) x 64 cols (n)
            int r = tid >> 4;
            int c = (tid & 15) << 2;
            int n = bn + c;
            float4 vb;
            if (n + 3 < N) {
                vb = *(const float4*)(B + (size_t)(k0 + r) * N + n);
            } else {
                const float* bp = B + (size_t)(k0 + r) * N;
                vb.x = (n < N) ? bp[n] : 0.f;
                vb.y = (n + 1 < N) ? bp[n + 1] : 0.f;
                vb.z = (n + 2 < N) ? bp[n + 2] : 0.f;
                vb.w = (n + 3 < N) ? bp[n + 3] : 0.f;
            }
            Bs[r][c] = vb.x; Bs[r][c + 1] = vb.y;
            Bs[r][c + 2] = vb.z; Bs[r][c + 3] = vb.w;
        } else {
            // B tile: rows are n (64), cols are k (16); store transposed
            int r = tid >> 2;
            int c = (tid & 3) << 2;
            int n = bn + r;
            float4 vb = make_float4(0.f, 0.f, 0.f, 0.f);
            if (n < N) vb = *(const float4*)(B + (size_t)n * K + k0 + c);
            Bs[c][r] = vb.x; Bs[c + 1][r] = vb.y;
            Bs[c + 2][r] = vb.z; Bs[c + 3][r] = vb.w;
        }
        __syncthreads();

#pragma unroll
        for (int kk = 0; kk < 16; kk++) {
            float a[4], b[4];
#pragma unroll
            for (int i = 0; i < 4; i++) {
                a[i] = As[kk][(ty << 2) + i];
                b[i] = Bs[kk][(tx << 2) + i];
            }
#pragma unroll
            for (int i = 0; i < 4; i++)
#pragma unroll
                for (int j = 0; j < 4; j++)
                    acc[i][j] = fmaf(a[i], b[j], acc[i][j]);
        }
        __syncthreads();
    }

#pragma unroll
    for (int i = 0; i < 4; i++) {
        int r = bm + (ty << 2) + i;
#pragma unroll
        for (int j = 0; j < 4; j++) {
            int c = bn + (tx << 2) + j;
            if (c < N) {
                float vv = acc[i][j] * alpha;
                if (RES) vv += Rsrc[(size_t)r * N + c];
                if (GELU_) vv = gelu_f(vv);
                C[(size_t)r * N + c] = vv;
            }
        }
    }
}

// ---------------------------------------------------------------------------
// Launch
// ---------------------------------------------------------------------------
extern "C" void kernel_launch(void* const* d_in, const int* in_sizes, int n_in,
                              void* d_out, int out_size) {
    (void)in_sizes; (void)n_in; (void)out_size;
    const int*   tokens = (const int*)d_in[0];
    const float* embed  = (const float*)d_in[1];
    const float* pos    = (const float*)d_in[2];
    const float* Wq     = (const float*)d_in[3];
    const float* Wk     = (const float*)d_in[4];
    const float* Wv     = (const float*)d_in[5];
    const float* Wo     = (const float*)d_in[6];
    const float* Ln1    = (const float*)d_in[7];
    const float* W1     = (const float*)d_in[8];
    const float* W2     = (const float*)d_in[9];
    const float* Ln2    = (const float*)d_in[10];
    const float* OutLn  = (const float*)d_in[11];
    float* out = (float*)d_out;

    float *x, *h, *q, *k, *v, *att, *ffn;
    cudaGetSymbolAddress((void**)&x,   g_x);
    cudaGetSymbolAddress((void**)&h,   g_h);
    cudaGetSymbolAddress((void**)&q,   g_q);
    cudaGetSymbolAddress((void**)&k,   g_k);
    cudaGetSymbolAddress((void**)&v,   g_v);
    cudaGetSymbolAddress((void**)&att, g_att);
    cudaGetSymbolAddress((void**)&ffn, g_ffn);

    embed_kernel<<<SEQ_L, 256>>>(tokens, embed, pos, x);

    dim3 grid_dd(DMODEL / 64, SEQ_L / 64);           // 12 x 32
    dim3 grid_df(FFDIM / 64, SEQ_L / 64);            // 48 x 32
    dim3 grid_dv((VOCAB + 63) / 64, SEQ_L / 64);     // 786 x 32
    dim3 grid_attn(SEQ_L, NHEAD);

    const float qscale = 0.125f;  // 1/sqrt(64)

    for (int layer = 0; layer < NLAYER; layer++) {
        const float* wq = Wq + (size_t)layer * DMODEL * DMODEL;
        const float* wk = Wk + (size_t)layer * DMODEL * DMODEL;
        const float* wv = Wv + (size_t)layer * DMODEL * DMODEL;
        const float* wo = Wo + (size_t)layer * DMODEL * DMODEL;
        const float* g1 = Ln1 + (size_t)layer * DMODEL;
        const float* w1 = W1 + (size_t)layer * DMODEL * FFDIM;
        const float* w2 = W2 + (size_t)layer * FFDIM * DMODEL;
        const float* g2 = Ln2 + (size_t)layer * DMODEL;

        ln_kernel<<<SEQ_L, 256>>>(x, g1, h);
        gemm_kernel<false, false, false><<<grid_dd, 256>>>(h, wq, q, nullptr,
            SEQ_L, DMODEL, DMODEL, qscale);
        gemm_kernel<false, false, false><<<grid_dd, 256>>>(h, wk, k, nullptr,
            SEQ_L, DMODEL, DMODEL, 1.0f);
        gemm_kernel<false, false, false><<<grid_dd, 256>>>(h, wv, v, nullptr,
            SEQ_L, DMODEL, DMODEL, 1.0f);
        attn_kernel<<<grid_attn, 256>>>(q, k, v, att);
        gemm_kernel<false, true, false><<<grid_dd, 256>>>(att, wo, x, x,
            SEQ_L, DMODEL, DMODEL, 1.0f);
        ln_kernel<<<SEQ_L, 256>>>(x, g2, h);
        gemm_kernel<false, false, true><<<grid_df, 256>>>(h, w1, ffn, nullptr,
            SEQ_L, FFDIM, DMODEL, 1.0f);
        gemm_kernel<false, true, false><<<grid_dd, 256>>>(ffn, w2, x, x,
            SEQ_L, DMODEL, FFDIM, 1.0f);
    }

    ln_kernel<<<SEQ_L, 256>>>(x, OutLn, h);
    // logits = h @ embed^T  (embed is [V, D] row-major -> NT GEMM)
    gemm_kernel<true, false, false><<<grid_dv, 256>>>(h, embed, out, nullptr,
        SEQ_L, VOCAB, DMODEL, 1.0f);
}

// round 4
// speedup vs baseline: 1.6160x; 1.6160x over previous
#include <cuda_runtime.h>
#include <cstdint>

// Problem dims
#define SEQ_L   2048
#define DMODEL  768
#define NHEAD   12
#define DHEAD   64
#define FFDIM   3072
#define VOCAB   50257
#define NLAYER  4

// ---------------------------------------------------------------------------
// Device-global scratch (no allocations allowed)
// ---------------------------------------------------------------------------
__device__ float g_x  [SEQ_L * DMODEL];
__device__ float g_h  [SEQ_L * DMODEL];
__device__ float g_q  [SEQ_L * DMODEL];
__device__ float g_k  [SEQ_L * DMODEL];
__device__ float g_v  [SEQ_L * DMODEL];
__device__ float g_att[SEQ_L * DMODEL];
__device__ float g_ffn[SEQ_L * FFDIM];

// ---------------------------------------------------------------------------
// Helpers
// ---------------------------------------------------------------------------
__device__ __forceinline__ float warp_reduce_sum(float v) {
#pragma unroll
    for (int o = 16; o > 0; o >>= 1) v += __shfl_xor_sync(0xffffffffu, v, o);
    return v;
}
__device__ __forceinline__ float warp_reduce_max(float v) {
#pragma unroll
    for (int o = 16; o > 0; o >>= 1) v = fmaxf(v, __shfl_xor_sync(0xffffffffu, v, o));
    return v;
}
__device__ __forceinline__ float gelu_f(float x) {
    float x3 = x * x * x;
    return 0.5f * x * (1.0f + tanhf(0.7978845608028654f * (x + 0.044715f * x3)));
}
__device__ __forceinline__ float to_tf32(float x) {
    float y;
    asm("cvt.rna.tf32.f32 %0, %1;" : "=f"(y) : "f"(x));
    return y;
}
__device__ __forceinline__ uint32_t smem_u32(const void* p) {
    uint32_t a;
    asm("{ .reg .u64 t; cvta.to.shared.u64 t, %1; cvt.u32.u64 %0, t; }"
        : "=r"(a) : "l"(p));
    return a;
}
__device__ __forceinline__ void ldmat_x4(uint32_t& r0, uint32_t& r1,
                                         uint32_t& r2, uint32_t& r3,
                                         uint32_t addr) {
    asm volatile("ldmatrix.sync.aligned.m8n8.x4.shared.b16 {%0,%1,%2,%3}, [%4];"
                 : "=r"(r0), "=r"(r1), "=r"(r2), "=r"(r3) : "r"(addr));
}
__device__ __forceinline__ void mma_tf32(float* c, const uint32_t* a,
                                         const uint32_t* b) {
    asm volatile(
        "mma.sync.aligned.m16n8k8.row.col.f32.tf32.tf32.f32 "
        "{%0,%1,%2,%3},{%4,%5,%6,%7},{%8,%9},{%0,%1,%2,%3};"
        : "+f"(c[0]), "+f"(c[1]), "+f"(c[2]), "+f"(c[3])
        : "r"(a[0]), "r"(a[1]), "r"(a[2]), "r"(a[3]), "r"(b[0]), "r"(b[1]));
}

// ---------------------------------------------------------------------------
// Embedding
// ---------------------------------------------------------------------------
__global__ void embed_kernel(const int* __restrict__ tokens,
                             const float* __restrict__ embed,
                             const float* __restrict__ pos,
                             float* __restrict__ x) {
    int l = blockIdx.x;
    int t = tokens[l];
    const float* er = embed + (size_t)t * DMODEL;
    const float* pr = pos + (size_t)l * DMODEL;
    float* xr = x + (size_t)l * DMODEL;
    for (int d = threadIdx.x; d < DMODEL; d += blockDim.x)
        xr[d] = er[d] + pr[d];
}

// ---------------------------------------------------------------------------
// LayerNorm
// ---------------------------------------------------------------------------
__global__ void ln_kernel(const float* __restrict__ x,
                          const float* __restrict__ gamma,
                          float* __restrict__ out) {
    int l = blockIdx.x;
    const float* row = x + (size_t)l * DMODEL;
    __shared__ float sb_s[8];
    __shared__ float sb_ss[8];
    __shared__ float s_mean, s_rstd;

    float s = 0.f, ss = 0.f;
    for (int d = threadIdx.x; d < DMODEL; d += blockDim.x) {
        float v = row[d];
        s += v; ss += v * v;
    }
    s = warp_reduce_sum(s);
    ss = warp_reduce_sum(ss);
    int warp = threadIdx.x >> 5;
    if ((threadIdx.x & 31) == 0) { sb_s[warp] = s; sb_ss[warp] = ss; }
    __syncthreads();
    if (threadIdx.x == 0) {
        float ts = 0.f, tss = 0.f;
        for (int i = 0; i < 8; i++) { ts += sb_s[i]; tss += sb_ss[i]; }
        float mean = ts * (1.0f / DMODEL);
        float var = tss * (1.0f / DMODEL) - mean * mean;
        s_mean = mean;
        s_rstd = rsqrtf(var + 1e-6f);
    }
    __syncthreads();
    float mean = s_mean, rstd = s_rstd;
    float* o = out + (size_t)l * DMODEL;
    for (int d = threadIdx.x; d < DMODEL; d += blockDim.x)
        o[d] = (row[d] - mean) * rstd * gamma[d];
}

// ---------------------------------------------------------------------------
// Causal attention (unchanged this round)
// ---------------------------------------------------------------------------
__global__ void attn_kernel(const float* __restrict__ q,
                            const float* __restrict__ k,
                            const float* __restrict__ v,
                            float* __restrict__ o) {
    int qi = blockIdx.x;
    int h = blockIdx.y;
    int tid = threadIdx.x;

    __shared__ float sq[DHEAD];
    __shared__ float sc[SEQ_L];
    __shared__ float rbuf[256];
    __shared__ float sred[8];
    __shared__ float s_stat;

    if (tid < DHEAD) sq[tid] = q[(size_t)qi * DMODEL + h * DHEAD + tid];
    __syncthreads();

    int nm = qi + 1;
    int warp = tid >> 5, lane = tid & 31;

    for (int m = warp; m < nm; m += 8) {
        const float* kp = k + (size_t)m * DMODEL + h * DHEAD;
        float p = sq[lane] * kp[lane] + sq[lane + 32] * kp[lane + 32];
        p = warp_reduce_sum(p);
        if (lane == 0) sc[m] = p;
    }
    __syncthreads();

    float mv = -3.4e38f;
    for (int m = tid; m < nm; m += 256) mv = fmaxf(mv, sc[m]);
    mv = warp_reduce_max(mv);
    if (lane == 0) sred[warp] = mv;
    __syncthreads();
    if (tid == 0) {
        float t = -3.4e38f;
        for (int i = 0; i < 8; i++) t = fmaxf(t, sred[i]);
        s_stat = t;
    }
    __syncthreads();
    mv = s_stat;

    float ssum = 0.f;
    for (int m = tid; m < nm; m += 256) {
        float e = expf(sc[m] - mv);
        sc[m] = e;
        ssum += e;
    }
    ssum = warp_reduce_sum(ssum);
    if (lane == 0) sred[warp] = ssum;
    __syncthreads();
    if (tid == 0) {
        float t = 0.f;
        for (int i = 0; i < 8; i++) t += sred[i];
        s_stat = t;
    }
    __syncthreads();
    float inv = 1.0f / s_stat;

    int d = tid & 63, part = tid >> 6;
    float acc = 0.f;
    for (int m = part; m < nm; m += 4)
        acc += sc[m] * v[(size_t)m * DMODEL + h * DHEAD + d];
    rbuf[tid] = acc;
    __syncthreads();
    if (part == 0)
        o[(size_t)qi * DMODEL + h * DHEAD + d] =
            (rbuf[d] + rbuf[64 + d] + rbuf[128 + d] + rbuf[192 + d]) * inv;
}

// ---------------------------------------------------------------------------
// TF32 tensor-core GEMM core.
//   C[M,N] = alpha * A[M,K] @ B (+ residual) (gelu)
//   BT=false: B is [K,N] row-major.  BT=true: B is [N,K] row-major (A@B^T).
// Block: 128 threads (4 warps), tile 128(M) x 128(N), BK=16, double-buffered.
// Warp tile 64x64: 4 m-frags x 8 n-frags of m16n8k8 tf32 mma.
// Smem rows padded to 20 floats -> conflict-free STS + ldmatrix.
// M % 128 == 0, K % 16 == 0 required; N arbitrary (guarded when BT).
// ---------------------------------------------------------------------------
#define LDW 20
#define SMEM_FLOATS (4 * 128 * LDW)   // 2 buffers x (A + B) = 10240 floats

template <bool BT, bool RES, bool GELU_>
__device__ __forceinline__ void gemm_core(const float* __restrict__ A,
                                          const float* __restrict__ B,
                                          float* __restrict__ C,
                                          const float* __restrict__ R,
                                          int M, int N, int K, float alpha,
                                          float* smem) {
    const int tid = threadIdx.x;
    const int lane = tid & 31;
    const int warp = tid >> 5;
    const int wm = (warp & 1) * 64;
    const int wn = (warp >> 1) * 64;
    const int bm = blockIdx.y * 128;
    const int bn = blockIdx.x * 128;

    float acc[4][8][4];
#pragma unroll
    for (int i = 0; i < 4; i++)
#pragma unroll
        for (int j = 0; j < 8; j++)
#pragma unroll
            for (int t = 0; t < 4; t++) acc[i][j][t] = 0.f;

    const uint32_t sbase = smem_u32(smem);
    float4 ra[4], rb[4];

    auto load_gl = [&](int k0) {
#pragma unroll
        for (int i = 0; i < 4; i++) {
            int qidx = tid + i * 128;
            int row = qidx >> 2, kq = (qidx & 3) << 2;
            ra[i] = *(const float4*)(A + (size_t)(bm + row) * K + k0 + kq);
            if (BT) {
                int n = bn + row;
                rb[i] = (n < N) ? *(const float4*)(B + (size_t)n * K + k0 + kq)
                                : make_float4(0.f, 0.f, 0.f, 0.f);
            } else {
                int kr = qidx >> 5, nq = (qidx & 31) << 2;
                rb[i] = *(const float4*)(B + (size_t)(k0 + kr) * N + bn + nq);
            }
        }
    };
    auto stage = [&](int buf) {
        float* sA = smem + buf * (128 * LDW);
        float* sB = smem + 2 * (128 * LDW) + buf * (128 * LDW);
#pragma unroll
        for (int i = 0; i < 4; i++) {
            int qidx = tid + i * 128;
            int row = qidx >> 2, kq = (qidx & 3) << 2;
            float4 va;
            va.x = to_tf32(ra[i].x); va.y = to_tf32(ra[i].y);
            va.z = to_tf32(ra[i].z); va.w = to_tf32(ra[i].w);
            *(float4*)(sA + row * LDW + kq) = va;
            if (BT) {
                float4 vb;
                vb.x = to_tf32(rb[i].x); vb.y = to_tf32(rb[i].y);
                vb.z = to_tf32(rb[i].z); vb.w = to_tf32(rb[i].w);
                *(float4*)(sB + row * LDW + kq) = vb;
            } else {
                int kr = qidx >> 5, nq = (qidx & 31) << 2;
                sB[(nq + 0) * LDW + kr] = to_tf32(rb[i].x);
                sB[(nq + 1) * LDW + kr] = to_tf32(rb[i].y);
                sB[(nq + 2) * LDW + kr] = to_tf32(rb[i].z);
                sB[(nq + 3) * LDW + kr] = to_tf32(rb[i].w);
            }
        }
    };

    const int nit = K >> 4;
    load_gl(0);
    stage(0);
    __syncthreads();

    const int lr = lane & 7;
    const int sel = lane >> 3;
    const int arof = (sel & 1) ? 8 : 0;
    const int acof = (sel & 2) ? 4 : 0;
    const int brof = (sel & 2) ? 8 : 0;
    const int bcof = (sel & 1) ? 4 : 0;

    for (int it = 0; it < nit; ++it) {
        int cur = it & 1;
        if (it + 1 < nit) load_gl((it + 1) << 4);

        uint32_t aU = sbase + (cur * (128 * LDW)) * 4;
        uint32_t bU = sbase + ((2 + cur) * (128 * LDW)) * 4;

#pragma unroll
        for (int kk8 = 0; kk8 < 2; ++kk8) {
            int kk = kk8 << 3;
            uint32_t aF[4][4], bF[8][2];
#pragma unroll
            for (int mt = 0; mt < 4; mt++) {
                uint32_t ad = aU + ((wm + mt * 16 + lr + arof) * LDW + kk + acof) * 4;
                ldmat_x4(aF[mt][0], aF[mt][1], aF[mt][2], aF[mt][3], ad);
            }
#pragma unroll
            for (int nt2 = 0; nt2 < 4; nt2++) {
                uint32_t bd = bU + ((wn + nt2 * 16 + lr + brof) * LDW + kk + bcof) * 4;
                uint32_t q0, q1, q2, q3;
                ldmat_x4(q0, q1, q2, q3, bd);
                bF[2 * nt2][0] = q0;     bF[2 * nt2][1] = q1;
                bF[2 * nt2 + 1][0] = q2; bF[2 * nt2 + 1][1] = q3;
            }
#pragma unroll
            for (int mt = 0; mt < 4; mt++)
#pragma unroll
                for (int nt = 0; nt < 8; nt++)
                    mma_tf32(acc[mt][nt], aF[mt], bF[nt]);
        }

        if (it + 1 < nit) stage(cur ^ 1);
        __syncthreads();
    }

    // Epilogue
#pragma unroll
    for (int mt = 0; mt < 4; mt++) {
        int r0 = bm + wm + mt * 16 + (lane >> 2);
#pragma unroll
        for (int nt = 0; nt < 8; nt++) {
            int c = bn + wn + nt * 8 + ((lane & 3) << 1);
#pragma unroll
            for (int half = 0; half < 2; half++) {
                int r = r0 + half * 8;
                float v0 = acc[mt][nt][half * 2 + 0] * alpha;
                float v1 = acc[mt][nt][half * 2 + 1] * alpha;
                if (RES) {
                    v0 += R[(size_t)r * N + c];
                    v1 += R[(size_t)r * N + c + 1];
                }
                if (GELU_) { v0 = gelu_f(v0); v1 = gelu_f(v1); }
                if (BT) {
                    if (c < N)     C[(size_t)r * N + c] = v0;
                    if (c + 1 < N) C[(size_t)r * N + c + 1] = v1;
                } else {
                    *(float2*)(C + (size_t)r * N + c) = make_float2(v0, v1);
                }
            }
        }
    }
}

template <bool BT, bool RES, bool GELU_>
__global__ __launch_bounds__(128, 2) void gemm_tf32(const float* __restrict__ A,
                                                    const float* __restrict__ B,
                                                    float* __restrict__ C,
                                                    const float* __restrict__ R,
                                                    int M, int N, int K,
                                                    float alpha) {
    __shared__ float smem[SMEM_FLOATS];
    gemm_core<BT, RES, GELU_>(A, B, C, R, M, N, K, alpha, smem);
}

// Fused QKV: grid.z selects which projection (fills the machine: 288 blocks)
__global__ __launch_bounds__(128, 2) void qkv_tf32(const float* __restrict__ h,
                                                   const float* __restrict__ wq,
                                                   const float* __restrict__ wk,
                                                   const float* __restrict__ wv,
                                                   float* __restrict__ q,
                                                   float* __restrict__ k,
                                                   float* __restrict__ v) {
    __shared__ float smem[SMEM_FLOATS];
    const float* B;
    float* C;
    float alpha;
    if (blockIdx.z == 0)      { B = wq; C = q; alpha = 0.125f; }
    else if (blockIdx.z == 1) { B = wk; C = k; alpha = 1.0f; }
    else                      { B = wv; C = v; alpha = 1.0f; }
    gemm_core<false, false, false>(h, B, C, nullptr, SEQ_L, DMODEL, DMODEL,
                                   alpha, smem);
}

// ---------------------------------------------------------------------------
// Launch
// ---------------------------------------------------------------------------
extern "C" void kernel_launch(void* const* d_in, const int* in_sizes, int n_in,
                              void* d_out, int out_size) {
    (void)in_sizes; (void)n_in; (void)out_size;
    const int*   tokens = (const int*)d_in[0];
    const float* embed  = (const float*)d_in[1];
    const float* pos    = (const float*)d_in[2];
    const float* Wq     = (const float*)d_in[3];
    const float* Wk     = (const float*)d_in[4];
    const float* Wv     = (const float*)d_in[5];
    const float* Wo     = (const float*)d_in[6];
    const float* Ln1    = (const float*)d_in[7];
    const float* W1     = (const float*)d_in[8];
    const float* W2     = (const float*)d_in[9];
    const float* Ln2    = (const float*)d_in[10];
    const float* OutLn  = (const float*)d_in[11];
    float* out = (float*)d_out;

    float *x, *h, *q, *k, *v, *att, *ffn;
    cudaGetSymbolAddress((void**)&x,   g_x);
    cudaGetSymbolAddress((void**)&h,   g_h);
    cudaGetSymbolAddress((void**)&q,   g_q);
    cudaGetSymbolAddress((void**)&k,   g_k);
    cudaGetSymbolAddress((void**)&v,   g_v);
    cudaGetSymbolAddress((void**)&att, g_att);
    cudaGetSymbolAddress((void**)&ffn, g_ffn);

    embed_kernel<<<SEQ_L, 256>>>(tokens, embed, pos, x);

    dim3 grid_dd(DMODEL / 128, SEQ_L / 128);              // 6 x 16
    dim3 grid_qkv(DMODEL / 128, SEQ_L / 128, 3);          // 6 x 16 x 3
    dim3 grid_df(FFDIM / 128, SEQ_L / 128);               // 24 x 16
    dim3 grid_dv((VOCAB + 127) / 128, SEQ_L / 128);       // 393 x 16
    dim3 grid_attn(SEQ_L, NHEAD);

    for (int layer = 0; layer < NLAYER; layer++) {
        const float* wq = Wq + (size_t)layer * DMODEL * DMODEL;
        const float* wk = Wk + (size_t)layer * DMODEL * DMODEL;
        const float* wv = Wv + (size_t)layer * DMODEL * DMODEL;
        const float* wo = Wo + (size_t)layer * DMODEL * DMODEL;
        const float* g1 = Ln1 + (size_t)layer * DMODEL;
        const float* w1 = W1 + (size_t)layer * DMODEL * FFDIM;
        const float* w2 = W2 + (size_t)layer * FFDIM * DMODEL;
        const float* g2 = Ln2 + (size_t)layer * DMODEL;

        ln_kernel<<<SEQ_L, 256>>>(x, g1, h);
        qkv_tf32<<<grid_qkv, 128>>>(h, wq, wk, wv, q, k, v);
        attn_kernel<<<grid_attn, 256>>>(q, k, v, att);
        gemm_tf32<false, true, false><<<grid_dd, 128>>>(att, wo, x, x,
            SEQ_L, DMODEL, DMODEL, 1.0f);
        ln_kernel<<<SEQ_L, 256>>>(x, g2, h);
        gemm_tf32<false, false, true><<<grid_df, 128>>>(h, w1, ffn, nullptr,
            SEQ_L, FFDIM, DMODEL, 1.0f);
        gemm_tf32<false, true, false><<<grid_dd, 128>>>(ffn, w2, x, x,
            SEQ_L, DMODEL, FFDIM, 1.0f);
    }

    ln_kernel<<<SEQ_L, 256>>>(x, OutLn, h);
    gemm_tf32<true, false, false><<<grid_dv, 128>>>(h, embed, out, nullptr,
        SEQ_L, VOCAB, DMODEL, 1.0f);
}

// round 5
// speedup vs baseline: 3.3989x; 2.1033x over previous
#include <cuda_runtime.h>
#include <cstdint>

// Problem dims
#define SEQ_L   2048
#define DMODEL  768
#define NHEAD   12
#define DHEAD   64
#define FFDIM   3072
#define VOCAB   50257
#define NLAYER  4

// ---------------------------------------------------------------------------
// Device-global scratch (no allocations allowed)
// ---------------------------------------------------------------------------
__device__ float g_x  [SEQ_L * DMODEL];
__device__ float g_h  [SEQ_L * DMODEL];
__device__ float g_q  [SEQ_L * DMODEL];
__device__ float g_k  [SEQ_L * DMODEL];
__device__ float g_v  [SEQ_L * DMODEL];
__device__ float g_att[SEQ_L * DMODEL];
__device__ float g_ffn[SEQ_L * FFDIM];

// ---------------------------------------------------------------------------
// Helpers
// ---------------------------------------------------------------------------
__device__ __forceinline__ float warp_reduce_sum(float v) {
#pragma unroll
    for (int o = 16; o > 0; o >>= 1) v += __shfl_xor_sync(0xffffffffu, v, o);
    return v;
}
__device__ __forceinline__ float gelu_f(float x) {
    float x3 = x * x * x;
    return 0.5f * x * (1.0f + tanhf(0.7978845608028654f * (x + 0.044715f * x3)));
}
__device__ __forceinline__ float to_tf32(float x) {
    float y;
    asm("cvt.rna.tf32.f32 %0, %1;" : "=f"(y) : "f"(x));
    return y;
}
__device__ __forceinline__ uint32_t smem_u32(const void* p) {
    uint32_t a;
    asm("{ .reg .u64 t; cvta.to.shared.u64 t, %1; cvt.u32.u64 %0, t; }"
        : "=r"(a) : "l"(p));
    return a;
}
__device__ __forceinline__ void ldmat_x4(uint32_t& r0, uint32_t& r1,
                                         uint32_t& r2, uint32_t& r3,
                                         uint32_t addr) {
    asm volatile("ldmatrix.sync.aligned.m8n8.x4.shared.b16 {%0,%1,%2,%3}, [%4];"
                 : "=r"(r0), "=r"(r1), "=r"(r2), "=r"(r3) : "r"(addr));
}
__device__ __forceinline__ void mma_tf32(float* c, const uint32_t* a,
                                         const uint32_t* b) {
    asm volatile(
        "mma.sync.aligned.m16n8k8.row.col.f32.tf32.tf32.f32 "
        "{%0,%1,%2,%3},{%4,%5,%6,%7},{%8,%9},{%0,%1,%2,%3};"
        : "+f"(c[0]), "+f"(c[1]), "+f"(c[2]), "+f"(c[3])
        : "r"(a[0]), "r"(a[1]), "r"(a[2]), "r"(a[3]), "r"(b[0]), "r"(b[1]));
}

// ---------------------------------------------------------------------------
// Embedding
// ---------------------------------------------------------------------------
__global__ void embed_kernel(const int* __restrict__ tokens,
                             const float* __restrict__ embed,
                             const float* __restrict__ pos,
                             float* __restrict__ x) {
    int l = blockIdx.x;
    int t = tokens[l];
    const float* er = embed + (size_t)t * DMODEL;
    const float* pr = pos + (size_t)l * DMODEL;
    float* xr = x + (size_t)l * DMODEL;
    for (int d = threadIdx.x; d < DMODEL; d += blockDim.x)
        xr[d] = er[d] + pr[d];
}

// ---------------------------------------------------------------------------
// LayerNorm
// ---------------------------------------------------------------------------
__global__ void ln_kernel(const float* __restrict__ x,
                          const float* __restrict__ gamma,
                          float* __restrict__ out) {
    int l = blockIdx.x;
    const float* row = x + (size_t)l * DMODEL;
    __shared__ float sb_s[8];
    __shared__ float sb_ss[8];
    __shared__ float s_mean, s_rstd;

    float s = 0.f, ss = 0.f;
    for (int d = threadIdx.x; d < DMODEL; d += blockDim.x) {
        float v = row[d];
        s += v; ss += v * v;
    }
    s = warp_reduce_sum(s);
    ss = warp_reduce_sum(ss);
    int warp = threadIdx.x >> 5;
    if ((threadIdx.x & 31) == 0) { sb_s[warp] = s; sb_ss[warp] = ss; }
    __syncthreads();
    if (threadIdx.x == 0) {
        float ts = 0.f, tss = 0.f;
        for (int i = 0; i < 8; i++) { ts += sb_s[i]; tss += sb_ss[i]; }
        float mean = ts * (1.0f / DMODEL);
        float var = tss * (1.0f / DMODEL) - mean * mean;
        s_mean = mean;
        s_rstd = rsqrtf(var + 1e-6f);
    }
    __syncthreads();
    float mean = s_mean, rstd = s_rstd;
    float* o = out + (size_t)l * DMODEL;
    for (int d = threadIdx.x; d < DMODEL; d += blockDim.x)
        o[d] = (row[d] - mean) * rstd * gamma[d];
}

// ---------------------------------------------------------------------------
// Flash attention (tf32 tensor cores).
// Block = 64 queries x 1 head. 128 threads = 4 warps, 16 q-rows each.
// Key tiles of 64. K tile and P share smem region sA; V transposed in sVt.
// ---------------------------------------------------------------------------
#define ALD 68   // smem row stride (floats): conflict-free fp32 ldmatrix

__global__ __launch_bounds__(128) void flash_attn(const float* __restrict__ q,
                                                  const float* __restrict__ k,
                                                  const float* __restrict__ v,
                                                  float* __restrict__ o) {
    const int qb = 31 - blockIdx.x;   // heaviest blocks first
    const int h = blockIdx.y;
    const int tid = threadIdx.x;
    const int lane = tid & 31;
    const int warp = tid >> 5;

    __shared__ float sA[64 * ALD];    // K tile, then P tile (and Q staging)
    __shared__ float sVt[64 * ALD];   // V tile transposed: sVt[d][key]
    const uint32_t sAu = smem_u32(sA);
    const uint32_t sVu = smem_u32(sVt);

    const int lr = lane & 7;
    const int sel = lane >> 3;
    const int arof = (sel & 1) ? 8 : 0;
    const int acof = (sel & 2) ? 4 : 0;
    const int brof = (sel & 2) ? 8 : 0;
    const int bcof = (sel & 1) ? 4 : 0;

    // ---- Stage Q tile (rows qb*64.., head h) and load A-fragments ----
    {
        const float* qp = q + (size_t)(qb * 64) * DMODEL + h * DHEAD;
#pragma unroll
        for (int i = 0; i < 8; i++) {
            int qi = tid + i * 128;
            int row = qi >> 4, c4 = (qi & 15) << 2;
            float4 vq = *(const float4*)(qp + (size_t)row * DMODEL + c4);
            vq.x = to_tf32(vq.x); vq.y = to_tf32(vq.y);
            vq.z = to_tf32(vq.z); vq.w = to_tf32(vq.w);
            *(float4*)(sA + row * ALD + c4) = vq;
        }
    }
    __syncthreads();
    uint32_t qF[8][4];
#pragma unroll
    for (int kk = 0; kk < 8; kk++) {
        uint32_t ad = sAu + ((warp * 16 + lr + arof) * ALD + kk * 8 + acof) * 4;
        ldmat_x4(qF[kk][0], qF[kk][1], qF[kk][2], qF[kk][3], ad);
    }

    // ---- Running stats + output accumulators ----
    float m0 = -1e30f, m1 = -1e30f, l0 = 0.f, l1 = 0.f;
    float oacc[8][4];
#pragma unroll
    for (int nt = 0; nt < 8; nt++)
#pragma unroll
        for (int c = 0; c < 4; c++) oacc[nt][c] = 0.f;

    const int ntiles = qb + 1;
    for (int t = 0; t < ntiles; t++) {
        // -- Global loads into registers --
        const float* kp = k + (size_t)(t * 64) * DMODEL + h * DHEAD;
        const float* vp = v + (size_t)(t * 64) * DMODEL + h * DHEAD;
        float4 kreg[8];
#pragma unroll
        for (int i = 0; i < 8; i++) {
            int qi = tid + i * 128;
            int row = qi >> 4, c4 = (qi & 15) << 2;
            kreg[i] = *(const float4*)(kp + (size_t)row * DMODEL + c4);
        }
        float4 vreg[2][4];
#pragma unroll
        for (int ii = 0; ii < 2; ii++) {
            int tile = tid + ii * 128;           // 0..255
            int ks = tile >> 4, ds = tile & 15;  // 4-key slab, 4-d slab
#pragma unroll
            for (int r = 0; r < 4; r++)
                vreg[ii][r] = *(const float4*)(vp + (size_t)(ks * 4 + r) * DMODEL + ds * 4);
        }

        __syncthreads();  // previous tile's P/V reads complete

        // -- Store K (tf32) and V transposed (tf32) --
#pragma unroll
        for (int i = 0; i < 8; i++) {
            int qi = tid + i * 128;
            int row = qi >> 4, c4 = (qi & 15) << 2;
            float4 vk = kreg[i];
            vk.x = to_tf32(vk.x); vk.y = to_tf32(vk.y);
            vk.z = to_tf32(vk.z); vk.w = to_tf32(vk.w);
            *(float4*)(sA + row * ALD + c4) = vk;
        }
#pragma unroll
        for (int ii = 0; ii < 2; ii++) {
            int tile = tid + ii * 128;
            int ks = tile >> 4, ds = tile & 15;
            float4 r0 = vreg[ii][0], r1 = vreg[ii][1];
            float4 r2 = vreg[ii][2], r3 = vreg[ii][3];
            float4 t0 = make_float4(to_tf32(r0.x), to_tf32(r1.x), to_tf32(r2.x), to_tf32(r3.x));
            float4 t1 = make_float4(to_tf32(r0.y), to_tf32(r1.y), to_tf32(r2.y), to_tf32(r3.y));
            float4 t2 = make_float4(to_tf32(r0.z), to_tf32(r1.z), to_tf32(r2.z), to_tf32(r3.z));
            float4 t3 = make_float4(to_tf32(r0.w), to_tf32(r1.w), to_tf32(r2.w), to_tf32(r3.w));
            *(float4*)(sVt + (ds * 4 + 0) * ALD + ks * 4) = t0;
            *(float4*)(sVt + (ds * 4 + 1) * ALD + ks * 4) = t1;
            *(float4*)(sVt + (ds * 4 + 2) * ALD + ks * 4) = t2;
            *(float4*)(sVt + (ds * 4 + 3) * ALD + ks * 4) = t3;
        }
        __syncthreads();

        // -- S = Q @ K^T (warp: 16 q-rows x 64 keys) --
        float sacc[8][4];
#pragma unroll
        for (int nt = 0; nt < 8; nt++)
#pragma unroll
            for (int c = 0; c < 4; c++) sacc[nt][c] = 0.f;
#pragma unroll
        for (int kk = 0; kk < 8; kk++) {
            uint32_t bF[8][2];
#pragma unroll
            for (int nt2 = 0; nt2 < 4; nt2++) {
                uint32_t bd = sAu + ((nt2 * 16 + lr + brof) * ALD + kk * 8 + bcof) * 4;
                uint32_t b0, b1, b2, b3;
                ldmat_x4(b0, b1, b2, b3, bd);
                bF[2 * nt2][0] = b0;     bF[2 * nt2][1] = b1;
                bF[2 * nt2 + 1][0] = b2; bF[2 * nt2 + 1][1] = b3;
            }
#pragma unroll
            for (int nt = 0; nt < 8; nt++)
                mma_tf32(sacc[nt], qF[kk], bF[nt]);
        }

        // -- Causal mask on diagonal tile --
        if (t == qb) {
            int r0 = warp * 16 + (lane >> 2);
#pragma unroll
            for (int nt = 0; nt < 8; nt++) {
                int kl = nt * 8 + ((lane & 3) << 1);
                if (kl > r0)         sacc[nt][0] = -1e30f;
                if (kl + 1 > r0)     sacc[nt][1] = -1e30f;
                if (kl > r0 + 8)     sacc[nt][2] = -1e30f;
                if (kl + 1 > r0 + 8) sacc[nt][3] = -1e30f;
            }
        }

        // -- Online softmax (row stats shared by each quad) --
        float tm0 = -1e30f, tm1 = -1e30f;
#pragma unroll
        for (int nt = 0; nt < 8; nt++) {
            tm0 = fmaxf(tm0, fmaxf(sacc[nt][0], sacc[nt][1]));
            tm1 = fmaxf(tm1, fmaxf(sacc[nt][2], sacc[nt][3]));
        }
        tm0 = fmaxf(tm0, __shfl_xor_sync(0xffffffffu, tm0, 1));
        tm0 = fmaxf(tm0, __shfl_xor_sync(0xffffffffu, tm0, 2));
        tm1 = fmaxf(tm1, __shfl_xor_sync(0xffffffffu, tm1, 1));
        tm1 = fmaxf(tm1, __shfl_xor_sync(0xffffffffu, tm1, 2));
        float nm0 = fmaxf(m0, tm0), nm1 = fmaxf(m1, tm1);
        float sc0 = __expf(m0 - nm0), sc1 = __expf(m1 - nm1);
        m0 = nm0; m1 = nm1;

        float p[8][4];
        float sum0 = 0.f, sum1 = 0.f;
#pragma unroll
        for (int nt = 0; nt < 8; nt++) {
            p[nt][0] = __expf(sacc[nt][0] - nm0);
            p[nt][1] = __expf(sacc[nt][1] - nm0);
            p[nt][2] = __expf(sacc[nt][2] - nm1);
            p[nt][3] = __expf(sacc[nt][3] - nm1);
            sum0 += p[nt][0] + p[nt][1];
            sum1 += p[nt][2] + p[nt][3];
        }
        sum0 += __shfl_xor_sync(0xffffffffu, sum0, 1);
        sum0 += __shfl_xor_sync(0xffffffffu, sum0, 2);
        sum1 += __shfl_xor_sync(0xffffffffu, sum1, 1);
        sum1 += __shfl_xor_sync(0xffffffffu, sum1, 2);
        l0 = l0 * sc0 + sum0;
        l1 = l1 * sc1 + sum1;
#pragma unroll
        for (int nt = 0; nt < 8; nt++) {
            oacc[nt][0] *= sc0; oacc[nt][1] *= sc0;
            oacc[nt][2] *= sc1; oacc[nt][3] *= sc1;
        }

        __syncthreads();  // all warps done reading K from sA

        // -- Write P (tf32) into sA (each warp its own 16 rows) --
        {
            int r0 = warp * 16 + (lane >> 2);
            int cb = (lane & 3) << 1;
#pragma unroll
            for (int nt = 0; nt < 8; nt++) {
                int col = nt * 8 + cb;
                *(float2*)(sA + r0 * ALD + col) =
                    make_float2(to_tf32(p[nt][0]), to_tf32(p[nt][1]));
                *(float2*)(sA + (r0 + 8) * ALD + col) =
                    make_float2(to_tf32(p[nt][2]), to_tf32(p[nt][3]));
            }
        }
        __syncwarp();

        // -- O += P @ V --
#pragma unroll
        for (int kk = 0; kk < 8; kk++) {
            uint32_t aP[4];
            uint32_t ad = sAu + ((warp * 16 + lr + arof) * ALD + kk * 8 + acof) * 4;
            ldmat_x4(aP[0], aP[1], aP[2], aP[3], ad);
            uint32_t bF[8][2];
#pragma unroll
            for (int nt2 = 0; nt2 < 4; nt2++) {
                uint32_t bd = sVu + ((nt2 * 16 + lr + brof) * ALD + kk * 8 + bcof) * 4;
                uint32_t b0, b1, b2, b3;
                ldmat_x4(b0, b1, b2, b3, bd);
                bF[2 * nt2][0] = b0;     bF[2 * nt2][1] = b1;
                bF[2 * nt2 + 1][0] = b2; bF[2 * nt2 + 1][1] = b3;
            }
#pragma unroll
            for (int nt = 0; nt < 8; nt++)
                mma_tf32(oacc[nt], aP, bF[nt]);
        }
    }

    // ---- Epilogue: normalize and store ----
    float inv0 = 1.0f / l0, inv1 = 1.0f / l1;
    int row0 = qb * 64 + warp * 16 + (lane >> 2);
    int cb = h * DHEAD + ((lane & 3) << 1);
#pragma unroll
    for (int nt = 0; nt < 8; nt++) {
        int col = cb + nt * 8;
        *(float2*)(o + (size_t)row0 * DMODEL + col) =
            make_float2(oacc[nt][0] * inv0, oacc[nt][1] * inv0);
        *(float2*)(o + (size_t)(row0 + 8) * DMODEL + col) =
            make_float2(oacc[nt][2] * inv1, oacc[nt][3] * inv1);
    }
}

// ---------------------------------------------------------------------------
// TF32 tensor-core GEMM (unchanged from R3 — validated)
// ---------------------------------------------------------------------------
#define LDW 20
#define SMEM_FLOATS (4 * 128 * LDW)

template <bool BT, bool RES, bool GELU_>
__device__ __forceinline__ void gemm_core(const float* __restrict__ A,
                                          const float* __restrict__ B,
                                          float* __restrict__ C,
                                          const float* __restrict__ R,
                                          int M, int N, int K, float alpha,
                                          float* smem) {
    const int tid = threadIdx.x;
    const int lane = tid & 31;
    const int warp = tid >> 5;
    const int wm = (warp & 1) * 64;
    const int wn = (warp >> 1) * 64;
    const int bm = blockIdx.y * 128;
    const int bn = blockIdx.x * 128;

    float acc[4][8][4];
#pragma unroll
    for (int i = 0; i < 4; i++)
#pragma unroll
        for (int j = 0; j < 8; j++)
#pragma unroll
            for (int t = 0; t < 4; t++) acc[i][j][t] = 0.f;

    const uint32_t sbase = smem_u32(smem);
    float4 ra[4], rb[4];

    auto load_gl = [&](int k0) {
#pragma unroll
        for (int i = 0; i < 4; i++) {
            int qidx = tid + i * 128;
            int row = qidx >> 2, kq = (qidx & 3) << 2;
            ra[i] = *(const float4*)(A + (size_t)(bm + row) * K + k0 + kq);
            if (BT) {
                int n = bn + row;
                rb[i] = (n < N) ? *(const float4*)(B + (size_t)n * K + k0 + kq)
                                : make_float4(0.f, 0.f, 0.f, 0.f);
            } else {
                int kr = qidx >> 5, nq = (qidx & 31) << 2;
                rb[i] = *(const float4*)(B + (size_t)(k0 + kr) * N + bn + nq);
            }
        }
    };
    auto stage = [&](int buf) {
        float* sA = smem + buf * (128 * LDW);
        float* sB = smem + 2 * (128 * LDW) + buf * (128 * LDW);
#pragma unroll
        for (int i = 0; i < 4; i++) {
            int qidx = tid + i * 128;
            int row = qidx >> 2, kq = (qidx & 3) << 2;
            float4 va;
            va.x = to_tf32(ra[i].x); va.y = to_tf32(ra[i].y);
            va.z = to_tf32(ra[i].z); va.w = to_tf32(ra[i].w);
            *(float4*)(sA + row * LDW + kq) = va;
            if (BT) {
                float4 vb;
                vb.x = to_tf32(rb[i].x); vb.y = to_tf32(rb[i].y);
                vb.z = to_tf32(rb[i].z); vb.w = to_tf32(rb[i].w);
                *(float4*)(sB + row * LDW + kq) = vb;
            } else {
                int kr = qidx >> 5, nq = (qidx & 31) << 2;
                sB[(nq + 0) * LDW + kr] = to_tf32(rb[i].x);
                sB[(nq + 1) * LDW + kr] = to_tf32(rb[i].y);
                sB[(nq + 2) * LDW + kr] = to_tf32(rb[i].z);
                sB[(nq + 3) * LDW + kr] = to_tf32(rb[i].w);
            }
        }
    };

    const int nit = K >> 4;
    load_gl(0);
    stage(0);
    __syncthreads();

    const int lr = lane & 7;
    const int sel = lane >> 3;
    const int arof = (sel & 1) ? 8 : 0;
    const int acof = (sel & 2) ? 4 : 0;
    const int brof = (sel & 2) ? 8 : 0;
    const int bcof = (sel & 1) ? 4 : 0;

    for (int it = 0; it < nit; ++it) {
        int cur = it & 1;
        if (it + 1 < nit) load_gl((it + 1) << 4);

        uint32_t aU = sbase + (cur * (128 * LDW)) * 4;
        uint32_t bU = sbase + ((2 + cur) * (128 * LDW)) * 4;

#pragma unroll
        for (int kk8 = 0; kk8 < 2; ++kk8) {
            int kk = kk8 << 3;
            uint32_t aF[4][4], bF[8][2];
#pragma unroll
            for (int mt = 0; mt < 4; mt++) {
                uint32_t ad = aU + ((wm + mt * 16 + lr + arof) * LDW + kk + acof) * 4;
                ldmat_x4(aF[mt][0], aF[mt][1], aF[mt][2], aF[mt][3], ad);
            }
#pragma unroll
            for (int nt2 = 0; nt2 < 4; nt2++) {
                uint32_t bd = bU + ((wn + nt2 * 16 + lr + brof) * LDW + kk + bcof) * 4;
                uint32_t q0, q1, q2, q3;
                ldmat_x4(q0, q1, q2, q3, bd);
                bF[2 * nt2][0] = q0;     bF[2 * nt2][1] = q1;
                bF[2 * nt2 + 1][0] = q2; bF[2 * nt2 + 1][1] = q3;
            }
#pragma unroll
            for (int mt = 0; mt < 4; mt++)
#pragma unroll
                for (int nt = 0; nt < 8; nt++)
                    mma_tf32(acc[mt][nt], aF[mt], bF[nt]);
        }

        if (it + 1 < nit) stage(cur ^ 1);
        __syncthreads();
    }

#pragma unroll
    for (int mt = 0; mt < 4; mt++) {
        int r0 = bm + wm + mt * 16 + (lane >> 2);
#pragma unroll
        for (int nt = 0; nt < 8; nt++) {
            int c = bn + wn + nt * 8 + ((lane & 3) << 1);
#pragma unroll
            for (int half = 0; half < 2; half++) {
                int r = r0 + half * 8;
                float v0 = acc[mt][nt][half * 2 + 0] * alpha;
                float v1 = acc[mt][nt][half * 2 + 1] * alpha;
                if (RES) {
                    v0 += R[(size_t)r * N + c];
                    v1 += R[(size_t)r * N + c + 1];
                }
                if (GELU_) { v0 = gelu_f(v0); v1 = gelu_f(v1); }
                if (BT) {
                    if (c < N)     C[(size_t)r * N + c] = v0;
                    if (c + 1 < N) C[(size_t)r * N + c + 1] = v1;
                } else {
                    *(float2*)(C + (size_t)r * N + c) = make_float2(v0, v1);
                }
            }
        }
    }
}

template <bool BT, bool RES, bool GELU_>
__global__ __launch_bounds__(128, 2) void gemm_tf32(const float* __restrict__ A,
                                                    const float* __restrict__ B,
                                                    float* __restrict__ C,
                                                    const float* __restrict__ R,
                                                    int M, int N, int K,
                                                    float alpha) {
    __shared__ float smem[SMEM_FLOATS];
    gemm_core<BT, RES, GELU_>(A, B, C, R, M, N, K, alpha, smem);
}

__global__ __launch_bounds__(128, 2) void qkv_tf32(const float* __restrict__ h,
                                                   const float* __restrict__ wq,
                                                   const float* __restrict__ wk,
                                                   const float* __restrict__ wv,
                                                   float* __restrict__ q,
                                                   float* __restrict__ k,
                                                   float* __restrict__ v) {
    __shared__ float smem[SMEM_FLOATS];
    const float* B;
    float* C;
    float alpha;
    if (blockIdx.z == 0)      { B = wq; C = q; alpha = 0.125f; }
    else if (blockIdx.z == 1) { B = wk; C = k; alpha = 1.0f; }
    else                      { B = wv; C = v; alpha = 1.0f; }
    gemm_core<false, false, false>(h, B, C, nullptr, SEQ_L, DMODEL, DMODEL,
                                   alpha, smem);
}

// ---------------------------------------------------------------------------
// Launch
// ---------------------------------------------------------------------------
extern "C" void kernel_launch(void* const* d_in, const int* in_sizes, int n_in,
                              void* d_out, int out_size) {
    (void)in_sizes; (void)n_in; (void)out_size;
    const int*   tokens = (const int*)d_in[0];
    const float* embed  = (const float*)d_in[1];
    const float* pos    = (const float*)d_in[2];
    const float* Wq     = (const float*)d_in[3];
    const float* Wk     = (const float*)d_in[4];
    const float* Wv     = (const float*)d_in[5];
    const float* Wo     = (const float*)d_in[6];
    const float* Ln1    = (const float*)d_in[7];
    const float* W1     = (const float*)d_in[8];
    const float* W2     = (const float*)d_in[9];
    const float* Ln2    = (const float*)d_in[10];
    const float* OutLn  = (const float*)d_in[11];
    float* out = (float*)d_out;

    float *x, *h, *q, *k, *v, *att, *ffn;
    cudaGetSymbolAddress((void**)&x,   g_x);
    cudaGetSymbolAddress((void**)&h,   g_h);
    cudaGetSymbolAddress((void**)&q,   g_q);
    cudaGetSymbolAddress((void**)&k,   g_k);
    cudaGetSymbolAddress((void**)&v,   g_v);
    cudaGetSymbolAddress((void**)&att, g_att);
    cudaGetSymbolAddress((void**)&ffn, g_ffn);

    embed_kernel<<<SEQ_L, 256>>>(tokens, embed, pos, x);

    dim3 grid_dd(DMODEL / 128, SEQ_L / 128);
    dim3 grid_qkv(DMODEL / 128, SEQ_L / 128, 3);
    dim3 grid_df(FFDIM / 128, SEQ_L / 128);
    dim3 grid_dv((VOCAB + 127) / 128, SEQ_L / 128);
    dim3 grid_attn(SEQ_L / 64, NHEAD);

    for (int layer = 0; layer < NLAYER; layer++) {
        const float* wq = Wq + (size_t)layer * DMODEL * DMODEL;
        const float* wk = Wk + (size_t)layer * DMODEL * DMODEL;
        const float* wv = Wv + (size_t)layer * DMODEL * DMODEL;
        const float* wo = Wo + (size_t)layer * DMODEL * DMODEL;
        const float* g1 = Ln1 + (size_t)layer * DMODEL;
        const float* w1 = W1 + (size_t)layer * DMODEL * FFDIM;
        const float* w2 = W2 + (size_t)layer * FFDIM * DMODEL;
        const float* g2 = Ln2 + (size_t)layer * DMODEL;

        ln_kernel<<<SEQ_L, 256>>>(x, g1, h);
        qkv_tf32<<<grid_qkv, 128>>>(h, wq, wk, wv, q, k, v);
        flash_attn<<<grid_attn, 128>>>(q, k, v, att);
        gemm_tf32<false, true, false><<<grid_dd, 128>>>(att, wo, x, x,
            SEQ_L, DMODEL, DMODEL, 1.0f);
        ln_kernel<<<SEQ_L, 256>>>(x, g2, h);
        gemm_tf32<false, false, true><<<grid_df, 128>>>(h, w1, ffn, nullptr,
            SEQ_L, FFDIM, DMODEL, 1.0f);
        gemm_tf32<false, true, false><<<grid_dd, 128>>>(ffn, w2, x, x,
            SEQ_L, DMODEL, FFDIM, 1.0f);
    }

    ln_kernel<<<SEQ_L, 256>>>(x, OutLn, h);
    gemm_tf32<true, false, false><<<grid_dv, 128>>>(h, embed, out, nullptr,
        SEQ_L, VOCAB, DMODEL, 1.0f);
}